// round 8
// baseline (speedup 1.0000x reference)
#include <cuda_runtime.h>
#include <cuda_fp16.h>
#include <math.h>

// Problem constants
#define NG    2048
#define NPG   512
#define CPG   128
#define CPG2  32

// Output layout (float32)
#define OFF_ZWHAT 0
#define OFF_ZMASK 131072
#define OFF_MU    262144
#define OFF_SIGMA 524288
#define OFF_F     786432

struct __align__(16) Smem {
    float w1l[64];       // [4][16]
    float b1l[16];
    float b1g[32];
    float b2l[64];
    float w1g[512];      // [16][32]
    float pos1l[2][384];
    float pos2l[2][96];
    int   idx1[2][128];
    int   cur[2][128];
    int   cur2[2][32];
    unsigned short ofs[2][128];
    unsigned short ofs2[2][32];
    unsigned short order[2][512];
    unsigned short order2[2][128];
    float agg[2][2048];     // stage1 means [128][16]
    float mean2[2][2048];   // [32][64] per glimpse
    float gsum[2][128];
    float fvec[2][256];
    float outv[2][256];
    union {                 // 16 KB
        __half2 f1h[2][2048];   // [128][16]h2 = [128][32] fp16
        float   psum[2][1024];  // [8][128]
    } A;
    union {                 // 32 KB
        float4  pts[2][512];
        __half2 h2[2][4096];    // [128][32]h2 = [128][64] fp16
        __half2 f2h[2][2048];   // [32][64]h2 = [32][128] fp16
    } B;
};

__device__ __forceinline__ float celu1(float x) {
    return fmaxf(x, 0.0f) + (__expf(fminf(x, 0.0f)) - 1.0f);
}

#define FMA4(Aacc, xs, wv) \
    { Aacc[0] = fmaf((xs), (wv).x, Aacc[0]); Aacc[1] = fmaf((xs), (wv).y, Aacc[1]); \
      Aacc[2] = fmaf((xs), (wv).z, Aacc[2]); Aacc[3] = fmaf((xs), (wv).w, Aacc[3]); }

__device__ __forceinline__ void pack2h2(float a0, float a1, float a2, float a3,
                                        __half2* dst) {
    const __half2 h0 = __floats2half2_rn(a0, a1);
    const __half2 h1 = __floats2half2_rn(a2, a3);
    float2 pk;
    pk.x = __uint_as_float(*reinterpret_cast<const unsigned int*>(&h0));
    pk.y = __uint_as_float(*reinterpret_cast<const unsigned int*>(&h1));
    *reinterpret_cast<float2*>(dst) = pk;
}

__device__ __forceinline__ void load4h(const __half2* src, float& x0, float& x1,
                                       float& x2, float& x3) {
    const float2 raw = *reinterpret_cast<const float2*>(src);
    const __half2 ha = *reinterpret_cast<const __half2*>(&raw.x);
    const __half2 hb = *reinterpret_cast<const __half2*>(&raw.y);
    const float2 fa = __half22float2(ha);
    const float2 fb = __half22float2(hb);
    x0 = fa.x; x1 = fa.y; x2 = fb.x; x3 = fb.y;
}

__global__ void __launch_bounds__(512, 2)
vae_fused_kernel(const float* __restrict__ rgb,  const float* __restrict__ pos,
                 const float* __restrict__ pos1, const float* __restrict__ pos2,
                 const int*   __restrict__ oi0,  const int* __restrict__ oi1,
                 const float* __restrict__ eps,
                 const float* __restrict__ W1l, const float* __restrict__ b1l,
                 const float* __restrict__ W1g, const float* __restrict__ b1g,
                 const float* __restrict__ W2l, const float* __restrict__ b2l,
                 const float* __restrict__ W2g, const float* __restrict__ b2g,
                 const float* __restrict__ W3l, const float* __restrict__ b3l,
                 const float* __restrict__ W3g, const float* __restrict__ b3g,
                 const float* __restrict__ Wlin, const float* __restrict__ blin,
                 float* __restrict__ out)
{
    extern __shared__ unsigned char smem_raw[];
    Smem& s = *reinterpret_cast<Smem*>(smem_raw);
    const int tid = threadIdx.x;
    const int gh  = tid >> 8;       // half id = glimpse within pair
    const int t   = tid & 255;      // index within half
    const int g0  = blockIdx.x * 2;
    const int g   = g0 + gh;

    // ---------------- preamble --------------------------------------------
    for (int i = tid; i < 64;  i += 512) s.w1l[i] = W1l[i];
    if (tid < 16) s.b1l[tid] = b1l[tid];
    if (tid < 32) s.b1g[tid] = b1g[tid];
    if (tid < 64) s.b2l[tid] = b2l[tid];
    for (int i = tid; i < 512; i += 512) s.w1g[i] = W1g[i];
    for (int i = t; i < 384; i += 256) s.pos1l[gh][i] = pos1[(size_t)g * 384 + i];
    if (t < 96)  s.pos2l[gh][t] = pos2[(size_t)g * 96 + t];
    if (t < 128) s.cur[gh][t] = 0;
    if (t < 32)  s.cur2[gh][t] = 0;
    __syncthreads();

    // ---------------- count phase (both glimpses concurrently) -------------
    if (t < 128) {
        const int c2 = (int)(oi1[(size_t)g * 128 + t] - g * CPG2);
        s.idx1[gh][t] = c2;
        atomicAdd(&s.cur2[gh][c2], 1);
    }
    for (int p = t; p < NPG; p += 256) {
        const size_t e = (size_t)g * NPG + p;
        float4 pt;
        pt.x = rgb[e];
        pt.y = pos[e * 3 + 0];
        pt.z = pos[e * 3 + 1];
        pt.w = pos[e * 3 + 2];
        s.B.pts[gh][p] = pt;
        atomicAdd(&s.cur[gh][oi0[e] - g * CPG], 1);
    }
    __syncthreads();

    // ---------------- prefix sums (one warp per scan per half) -------------
    {
        const int lane = t & 31;
        if (t < 32) {
            int v0 = s.cur[gh][lane * 4 + 0], v1 = s.cur[gh][lane * 4 + 1];
            int v2 = s.cur[gh][lane * 4 + 2], v3 = s.cur[gh][lane * 4 + 3];
            int lsum = v0 + v1 + v2 + v3;
            int sc = lsum;
            #pragma unroll
            for (int off = 1; off < 32; off <<= 1) {
                int n = __shfl_up_sync(0xffffffffu, sc, off);
                if (lane >= off) sc += n;
            }
            int e0 = sc - lsum;
            int e1 = e0 + v0, e2 = e1 + v1, e3 = e2 + v2;
            s.ofs[gh][lane * 4 + 0] = (unsigned short)e0; s.cur[gh][lane * 4 + 0] = e0;
            s.ofs[gh][lane * 4 + 1] = (unsigned short)e1; s.cur[gh][lane * 4 + 1] = e1;
            s.ofs[gh][lane * 4 + 2] = (unsigned short)e2; s.cur[gh][lane * 4 + 2] = e2;
            s.ofs[gh][lane * 4 + 3] = (unsigned short)e3; s.cur[gh][lane * 4 + 3] = e3;
        } else if (t < 64) {
            int v = s.cur2[gh][lane];
            int sc = v;
            #pragma unroll
            for (int off = 1; off < 32; off <<= 1) {
                int n = __shfl_up_sync(0xffffffffu, sc, off);
                if (lane >= off) sc += n;
            }
            s.ofs2[gh][lane] = (unsigned short)(sc - v);
            s.cur2[gh][lane] = sc - v;
        }
    }
    __syncthreads();

    // ---------------- scatter passes ----------------------------------------
    for (int p = t; p < NPG; p += 256) {
        const int c = oi0[(size_t)g * NPG + p] - g * CPG;
        const int slot = atomicAdd(&s.cur[gh][c], 1);
        s.order[gh][slot] = (unsigned short)p;
    }
    if (t < 128) {
        const int slot = atomicAdd(&s.cur2[gh][s.idx1[gh][t]], 1);
        s.order2[gh][slot] = (unsigned short)t;
    }
    __syncthreads();

    // ---------------- stage 1: gather edge MLP (4->16) + mean ---------------
    {
        const int c  = t >> 1;
        const int hf = t & 1;
        const int beg = (int)s.ofs[gh][c];
        const int n   = s.cur[gh][c] - beg;
        const float cx = s.pos1l[gh][c * 3 + 0];
        const float cy = s.pos1l[gh][c * 3 + 1];
        const float cz = s.pos1l[gh][c * 3 + 2];
        const float inv = 1.0f / fmaxf((float)n, 1.0f);
        #pragma unroll
        for (int pass = 0; pass < 2; pass++) {
            const int jb = hf * 8 + pass * 4;
            float wb[4], w0r[4], w1r[4], w2r[4], w3r[4];
            #pragma unroll
            for (int j4 = 0; j4 < 4; j4++) {
                const int j = jb + j4;
                wb[j4]  = s.b1l[j];
                w0r[j4] = s.w1l[j];
                w1r[j4] = s.w1l[16 + j];
                w2r[j4] = s.w1l[32 + j];
                w3r[j4] = s.w1l[48 + j];
            }
            float acc[4] = {0.f, 0.f, 0.f, 0.f};
            for (int i = 0; i < n; i++) {
                const float4 pt = s.B.pts[gh][(int)s.order[gh][beg + i]];
                const float rx = pt.y - cx, ry = pt.z - cy, rz = pt.w - cz;
                #pragma unroll
                for (int j4 = 0; j4 < 4; j4++) {
                    float a = wb[j4];
                    a = fmaf(pt.x, w0r[j4], a);
                    a = fmaf(rx,   w1r[j4], a);
                    a = fmaf(ry,   w2r[j4], a);
                    a = fmaf(rz,   w3r[j4], a);
                    acc[j4] += celu1(a);
                }
            }
            #pragma unroll
            for (int j4 = 0; j4 < 4; j4++)
                s.agg[gh][c * 16 + jb + j4] = acc[j4] * inv;
        }
    }
    __syncthreads();

    // ---------------- stage 2: f1 = celu(mean1 @ W1g + b1g) -> fp16 ---------
    {
        const int jq = t & 7;
        const int cg = t >> 3;
        const float4* Wq = reinterpret_cast<const float4*>(s.w1g); // [16][8]
        float acc[4][4];
        #pragma unroll
        for (int c4 = 0; c4 < 4; c4++)
            #pragma unroll
            for (int u = 0; u < 4; u++) acc[c4][u] = s.b1g[jq * 4 + u];
        #pragma unroll
        for (int k = 0; k < 16; k++) {
            const float4 wv = Wq[k * 8 + jq];
            #pragma unroll
            for (int c4 = 0; c4 < 4; c4++) {
                const float x = s.agg[gh][(cg * 4 + c4) * 16 + k];
                FMA4(acc[c4], x, wv);
            }
        }
        #pragma unroll
        for (int c4 = 0; c4 < 4; c4++) {
            const int c = cg * 4 + c4;
            pack2h2(celu1(acc[c4][0]), celu1(acc[c4][1]),
                    celu1(acc[c4][2]), celu1(acc[c4][3]),
                    &s.A.f1h[gh][c * 16 + jq * 2]);
        }
    }
    __syncthreads();

    // ---------------- stage 3a: edge MLP (35->64) into h2 (fp16) ------------
    {
        const int jq = t & 15;
        const int eg = t >> 4;          // 16 groups x 8 edges, 2 passes of 4
        const float4* Wq = reinterpret_cast<const float4*>(W2l);   // [35][16]
        const float4 bb = reinterpret_cast<const float4*>(s.b2l)[jq];
        #pragma unroll
        for (int pass = 0; pass < 2; pass++) {
            const int ebase = eg * 8 + pass * 4;
            float acc[4][4];
            #pragma unroll
            for (int e = 0; e < 4; e++) {
                acc[e][0] = bb.x; acc[e][1] = bb.y; acc[e][2] = bb.z; acc[e][3] = bb.w;
            }
            #pragma unroll
            for (int kq = 0; kq < 8; kq++) {
                const float4 wa = Wq[(kq * 4 + 0) * 16 + jq];
                const float4 wb = Wq[(kq * 4 + 1) * 16 + jq];
                const float4 wc = Wq[(kq * 4 + 2) * 16 + jq];
                const float4 wd = Wq[(kq * 4 + 3) * 16 + jq];
                #pragma unroll
                for (int e = 0; e < 4; e++) {
                    float x0, x1, x2, x3;
                    load4h(&s.A.f1h[gh][(ebase + e) * 16 + kq * 2], x0, x1, x2, x3);
                    FMA4(acc[e], x0, wa);
                    FMA4(acc[e], x1, wb);
                    FMA4(acc[e], x2, wc);
                    FMA4(acc[e], x3, wd);
                }
            }
            #pragma unroll
            for (int k2 = 0; k2 < 3; k2++) {
                const float4 wv = Wq[(32 + k2) * 16 + jq];
                #pragma unroll
                for (int e = 0; e < 4; e++) {
                    const int ee = ebase + e;
                    const float r = s.pos1l[gh][ee * 3 + k2]
                                  - s.pos2l[gh][s.idx1[gh][ee] * 3 + k2];
                    FMA4(acc[e], r, wv);
                }
            }
            #pragma unroll
            for (int e = 0; e < 4; e++) {
                const int ee = ebase + e;
                pack2h2(celu1(acc[e][0]), celu1(acc[e][1]),
                        celu1(acc[e][2]), celu1(acc[e][3]),
                        &s.B.h2[gh][ee * 32 + jq * 2]);
            }
        }
    }
    __syncthreads();

    // ---------------- stage 3b: gather-reduce h2 -> mean2 [32][64] ----------
    {
        const int c2 = t >> 3;
        const int f8 = t & 7;
        const int beg = (int)s.ofs2[gh][c2];
        const int n   = s.cur2[gh][c2] - beg;
        float acc[8];
        #pragma unroll
        for (int k = 0; k < 8; k++) acc[k] = 0.0f;
        for (int i = 0; i < n; i++) {
            const int e = (int)s.order2[gh][beg + i];
            float x0, x1, x2, x3, x4, x5, x6, x7;
            load4h(&s.B.h2[gh][e * 32 + f8 * 4],     x0, x1, x2, x3);
            load4h(&s.B.h2[gh][e * 32 + f8 * 4 + 2], x4, x5, x6, x7);
            acc[0] += x0; acc[1] += x1; acc[2] += x2; acc[3] += x3;
            acc[4] += x4; acc[5] += x5; acc[6] += x6; acc[7] += x7;
        }
        const float inv = 1.0f / fmaxf((float)n, 1.0f);
        float4 o0, o1;
        o0.x = acc[0] * inv; o0.y = acc[1] * inv; o0.z = acc[2] * inv; o0.w = acc[3] * inv;
        o1.x = acc[4] * inv; o1.y = acc[5] * inv; o1.z = acc[6] * inv; o1.w = acc[7] * inv;
        reinterpret_cast<float4*>(&s.mean2[gh][c2 * 64 + f8 * 8])[0] = o0;
        reinterpret_cast<float4*>(&s.mean2[gh][c2 * 64 + f8 * 8])[1] = o1;
    }
    __syncthreads();

    // ============ joint stages 4-7 (512 threads over both glimpses) =========

    // stage 4: f2 = celu(mean2 @ W2g + b2g) [2][32][128] -> fp16
    {
        const int jq  = tid & 31;
        const int grp = tid >> 5;       // 16 groups x 4 rows of 64
        const float4* Wq = reinterpret_cast<const float4*>(W2g);  // [64][32]
        const float4 bb = reinterpret_cast<const float4*>(b2g)[jq];
        float acc[4][4];
        #pragma unroll
        for (int c4 = 0; c4 < 4; c4++) {
            acc[c4][0] = bb.x; acc[c4][1] = bb.y; acc[c4][2] = bb.z; acc[c4][3] = bb.w;
        }
        #pragma unroll 4
        for (int kq = 0; kq < 16; kq++) {
            const float4 wa = Wq[(kq * 4 + 0) * 32 + jq];
            const float4 wb = Wq[(kq * 4 + 1) * 32 + jq];
            const float4 wc = Wq[(kq * 4 + 2) * 32 + jq];
            const float4 wd = Wq[(kq * 4 + 3) * 32 + jq];
            #pragma unroll
            for (int c4 = 0; c4 < 4; c4++) {
                const int r  = grp * 4 + c4;
                const int gi = r >> 5, cl = r & 31;
                const float4 x = reinterpret_cast<const float4*>(s.mean2[gi])[cl * 16 + kq];
                FMA4(acc[c4], x.x, wa);
                FMA4(acc[c4], x.y, wb);
                FMA4(acc[c4], x.z, wc);
                FMA4(acc[c4], x.w, wd);
            }
        }
        #pragma unroll
        for (int c4 = 0; c4 < 4; c4++) {
            const int r  = grp * 4 + c4;
            const int gi = r >> 5, cl = r & 31;
            pack2h2(celu1(acc[c4][0]), celu1(acc[c4][1]),
                    celu1(acc[c4][2]), celu1(acc[c4][3]),
                    &s.B.f2h[gi][cl * 64 + jq * 2]);
        }
    }
    __syncthreads();

    // stage 5: level-3 edge MLP (131->128) + partial means
    {
        const int jq = tid & 31;
        const int eg = tid >> 5;        // 16 groups x 4 edges
        const int gi = eg >> 3;
        const int e4 = eg & 7;
        const float4* Wq = reinterpret_cast<const float4*>(W3l);  // [131][32]
        const float4 bb = reinterpret_cast<const float4*>(b3l)[jq];
        float acc[4][4];
        #pragma unroll
        for (int e = 0; e < 4; e++) {
            acc[e][0] = bb.x; acc[e][1] = bb.y; acc[e][2] = bb.z; acc[e][3] = bb.w;
        }
        #pragma unroll 4
        for (int kq = 0; kq < 32; kq++) {
            const float4 wa = Wq[(kq * 4 + 0) * 32 + jq];
            const float4 wb = Wq[(kq * 4 + 1) * 32 + jq];
            const float4 wc = Wq[(kq * 4 + 2) * 32 + jq];
            const float4 wd = Wq[(kq * 4 + 3) * 32 + jq];
            #pragma unroll
            for (int e = 0; e < 4; e++) {
                const int ee = e4 * 4 + e;
                float x0, x1, x2, x3;
                load4h(&s.B.f2h[gi][ee * 64 + kq * 2], x0, x1, x2, x3);
                FMA4(acc[e], x0, wa);
                FMA4(acc[e], x1, wb);
                FMA4(acc[e], x2, wc);
                FMA4(acc[e], x3, wd);
            }
        }
        #pragma unroll
        for (int k2 = 0; k2 < 3; k2++) {
            const float4 wv = Wq[(128 + k2) * 32 + jq];
            #pragma unroll
            for (int e = 0; e < 4; e++) {
                const float r = s.pos2l[gi][(e4 * 4 + e) * 3 + k2];
                FMA4(acc[e], r, wv);
            }
        }
        float4 pv;
        pv.x = celu1(acc[0][0]) + celu1(acc[1][0]) + celu1(acc[2][0]) + celu1(acc[3][0]);
        pv.y = celu1(acc[0][1]) + celu1(acc[1][1]) + celu1(acc[2][1]) + celu1(acc[3][1]);
        pv.z = celu1(acc[0][2]) + celu1(acc[1][2]) + celu1(acc[2][2]) + celu1(acc[3][2]);
        pv.w = celu1(acc[0][3]) + celu1(acc[1][3]) + celu1(acc[2][3]) + celu1(acc[3][3]);
        reinterpret_cast<float4*>(&s.A.psum[gi][e4 * 128 + jq * 4])[0] = pv;
    }
    __syncthreads();
    if (tid < 256) {
        const int gi = tid >> 7;
        const int j  = tid & 127;
        float sum = 0.0f;
        #pragma unroll
        for (int e = 0; e < 8; e++) sum += s.A.psum[gi][e * 128 + j];
        s.gsum[gi][j] = sum;
    }
    __syncthreads();

    // stage 6: f = celu((gsum/32) @ W3g + b3g), one glimpse per half
    {
        const int j = t;
        float sum = 0.0f;
        #pragma unroll 8
        for (int k = 0; k < 128; k++)
            sum = fmaf(s.gsum[gh][k], W3g[k * 256 + j], sum);
        const float fv = celu1(fmaf(sum, 0.03125f, b3g[j]));
        s.fvec[gh][j] = fv;
        out[OFF_F + (size_t)g * 256 + j] = fv;
    }
    __syncthreads();

    // stage 7: out = f @ Wlin + blin, one glimpse per half
    {
        const int j = t;
        float acc = blin[j];
        #pragma unroll 8
        for (int k = 0; k < 256; k++)
            acc = fmaf(s.fvec[gh][k], Wlin[k * 256 + j], acc);
        s.outv[gh][j] = acc;
    }
    __syncthreads();

    if (tid < 256) {
        const int gi = tid >> 7;
        const int j  = tid & 127;
        const size_t gg = g0 + gi;
        const float mu = s.outv[gi][j];
        const float sg = s.outv[gi][128 + j];
        const float sigma = fmaxf(sg, 0.0f) + log1pf(__expf(-fabsf(sg)));
        const float z = fmaf(sigma, eps[gg * 128 + j], mu);
        out[OFF_MU    + gg * 128 + j] = mu;
        out[OFF_SIGMA + gg * 128 + j] = sigma;
        if (j < 64) out[OFF_ZWHAT + gg * 64 + j] = z;
        else        out[OFF_ZMASK + gg * 64 + (j - 64)] = z;
    }
}

extern "C" void kernel_launch(void* const* d_in, const int* in_sizes, int n_in,
                              void* d_out, int out_size)
{
    const float* rgb  = (const float*)d_in[0];
    const float* pos  = (const float*)d_in[1];
    const float* pos1 = (const float*)d_in[2];
    const float* pos2 = (const float*)d_in[3];
    const int*   oi0  = (const int*)  d_in[4];
    const int*   oi1  = (const int*)  d_in[5];
    const float* eps  = (const float*)d_in[7];
    const float* W1l  = (const float*)d_in[8];
    const float* b1l  = (const float*)d_in[9];
    const float* W1g  = (const float*)d_in[10];
    const float* b1g  = (const float*)d_in[11];
    const float* W2l  = (const float*)d_in[12];
    const float* b2l  = (const float*)d_in[13];
    const float* W2g  = (const float*)d_in[14];
    const float* b2g  = (const float*)d_in[15];
    const float* W3l  = (const float*)d_in[16];
    const float* b3l  = (const float*)d_in[17];
    const float* W3g  = (const float*)d_in[18];
    const float* b3g  = (const float*)d_in[19];
    const float* Wlin = (const float*)d_in[20];
    const float* blin = (const float*)d_in[21];
    float* out = (float*)d_out;

    cudaFuncSetAttribute(vae_fused_kernel,
                         cudaFuncAttributeMaxDynamicSharedMemorySize,
                         (int)sizeof(Smem));
    vae_fused_kernel<<<NG / 2, 512, sizeof(Smem)>>>(
        rgb, pos, pos1, pos2, oi0, oi1, eps,
        W1l, b1l, W1g, b1g, W2l, b2l, W2g, b2g,
        W3l, b3l, W3g, b3g, Wlin, blin, out);
}

// round 9
// speedup vs baseline: 2.2634x; 2.2634x over previous
#include <cuda_runtime.h>
#include <cuda_fp16.h>
#include <math.h>

// Problem constants
#define NG    2048
#define NPG   512
#define CPG   128
#define CPG2  32

// Output layout (float32)
#define OFF_ZWHAT 0
#define OFF_ZMASK 131072
#define OFF_MU    262144
#define OFF_SIGMA 524288
#define OFF_F     786432

struct __align__(16) Smem {
    float w1l[64];      // [4][16]
    float b1l[16];
    float b1g[32];
    float b2l[64];
    float w1g[512];     // [16][32]
    float pos1l[384];   // [128][3]      (per-glimpse, reloaded)
    float pos2l2[192];  // [2][32][3]    (both glimpses)
    int   idx1[128];
    int   cur[128];
    int   cur2[32];
    unsigned short ofs[128];
    unsigned short ofs2[32];
    unsigned short order[512];
    unsigned short order2[128];
    float agg[2048];        // stage1 mean [128][16] (per-glimpse)
    __half2 mean2h[2048];   // [2][32][32h2] = [2][32][64] fp16
    float gsum[256];        // [2][128]
    float fvec[512];        // [2][256]
    float outv[512];        // [2][256]
    union {                 // 8 KB
        __half2 f1h[2048];  // [128][16h2] per-glimpse stage2->3a
        float   psum[2048]; // [2][8][128] joint stage5
    } A;
    union {                 // 16 KB
        float4  pts[512];   // per-glimpse load->stage1 (8 KB)
        __half2 h2[4096];   // [128][32h2] per-glimpse stage3a->3b
        __half2 f2h[4096];  // [2][32][64h2] joint stage4->5
    } B;
};

__device__ __forceinline__ float celu1(float x) {
    return fmaxf(x, 0.0f) + (__expf(fminf(x, 0.0f)) - 1.0f);
}

#define FMA4(Aacc, xs, wv) \
    { Aacc[0] = fmaf((xs), (wv).x, Aacc[0]); Aacc[1] = fmaf((xs), (wv).y, Aacc[1]); \
      Aacc[2] = fmaf((xs), (wv).z, Aacc[2]); Aacc[3] = fmaf((xs), (wv).w, Aacc[3]); }

__device__ __forceinline__ void pack2h2(float a0, float a1, float a2, float a3,
                                        __half2* dst) {
    const __half2 h0 = __floats2half2_rn(a0, a1);
    const __half2 h1 = __floats2half2_rn(a2, a3);
    float2 pk;
    pk.x = __uint_as_float(*reinterpret_cast<const unsigned int*>(&h0));
    pk.y = __uint_as_float(*reinterpret_cast<const unsigned int*>(&h1));
    *reinterpret_cast<float2*>(dst) = pk;
}

__device__ __forceinline__ void load4h(const __half2* src, float& x0, float& x1,
                                       float& x2, float& x3) {
    const float2 raw = *reinterpret_cast<const float2*>(src);
    const __half2 ha = *reinterpret_cast<const __half2*>(&raw.x);
    const __half2 hb = *reinterpret_cast<const __half2*>(&raw.y);
    const float2 fa = __half22float2(ha);
    const float2 fb = __half22float2(hb);
    x0 = fa.x; x1 = fa.y; x2 = fb.x; x3 = fb.y;
}

__global__ void __launch_bounds__(256, 3)
vae_fused_kernel(const float* __restrict__ rgb,  const float* __restrict__ pos,
                 const float* __restrict__ pos1, const float* __restrict__ pos2,
                 const int*   __restrict__ oi0,  const int* __restrict__ oi1,
                 const float* __restrict__ eps,
                 const float* __restrict__ W1l, const float* __restrict__ b1l,
                 const float* __restrict__ W1g, const float* __restrict__ b1g,
                 const float* __restrict__ W2l, const float* __restrict__ b2l,
                 const float* __restrict__ W2g, const float* __restrict__ b2g,
                 const float* __restrict__ W3l, const float* __restrict__ b3l,
                 const float* __restrict__ W3g, const float* __restrict__ b3g,
                 const float* __restrict__ Wlin, const float* __restrict__ blin,
                 float* __restrict__ out)
{
    extern __shared__ unsigned char smem_raw[];
    Smem& s = *reinterpret_cast<Smem*>(smem_raw);
    const int tid  = threadIdx.x;
    const int lane = tid & 31;
    const int g0   = blockIdx.x * 2;

    // ---------------- preamble: weights + both glimpses' level-2 centers ----
    for (int i = tid; i < 64;  i += 256) s.w1l[i] = W1l[i];
    if (tid < 16) s.b1l[tid] = b1l[tid];
    if (tid < 32) s.b1g[tid] = b1g[tid];
    if (tid < 64) s.b2l[tid] = b2l[tid];
    for (int i = tid; i < 512; i += 256) s.w1g[i] = W1g[i];
    if (tid < 192) s.pos2l2[tid] = pos2[(size_t)g0 * 96 + tid];

    // ============ per-glimpse stages 1-3 (sequential, buffers reused) =======
    for (int gi = 0; gi < 2; gi++) {
        const int g = g0 + gi;
        __syncthreads();
        if (tid < 128) s.cur[tid] = 0;
        if (tid < 32)  s.cur2[tid] = 0;
        for (int i = tid; i < 384; i += 256) s.pos1l[i] = pos1[(size_t)g * 384 + i];
        __syncthreads();

        // count phase
        if (tid < 128) {
            const int c2 = (int)(oi1[(size_t)g * 128 + tid] - g * CPG2);
            s.idx1[tid] = c2;
            atomicAdd(&s.cur2[c2], 1);
        }
        for (int p = tid; p < NPG; p += 256) {
            const size_t e = (size_t)g * NPG + p;
            float4 pt;
            pt.x = rgb[e];
            pt.y = pos[e * 3 + 0];
            pt.z = pos[e * 3 + 1];
            pt.w = pos[e * 3 + 2];
            s.B.pts[p] = pt;
            atomicAdd(&s.cur[oi0[e] - g * CPG], 1);
        }
        __syncthreads();

        // prefix sums; cur becomes alloc cursor
        if (tid < 32) {
            int v0 = s.cur[lane * 4 + 0], v1 = s.cur[lane * 4 + 1];
            int v2 = s.cur[lane * 4 + 2], v3 = s.cur[lane * 4 + 3];
            int lsum = v0 + v1 + v2 + v3;
            int sc = lsum;
            #pragma unroll
            for (int off = 1; off < 32; off <<= 1) {
                int n = __shfl_up_sync(0xffffffffu, sc, off);
                if (lane >= off) sc += n;
            }
            int e0 = sc - lsum;
            int e1 = e0 + v0, e2 = e1 + v1, e3 = e2 + v2;
            s.ofs[lane * 4 + 0] = (unsigned short)e0; s.cur[lane * 4 + 0] = e0;
            s.ofs[lane * 4 + 1] = (unsigned short)e1; s.cur[lane * 4 + 1] = e1;
            s.ofs[lane * 4 + 2] = (unsigned short)e2; s.cur[lane * 4 + 2] = e2;
            s.ofs[lane * 4 + 3] = (unsigned short)e3; s.cur[lane * 4 + 3] = e3;
        } else if (tid < 64) {
            int v = s.cur2[lane];
            int sc = v;
            #pragma unroll
            for (int off = 1; off < 32; off <<= 1) {
                int n = __shfl_up_sync(0xffffffffu, sc, off);
                if (lane >= off) sc += n;
            }
            s.ofs2[lane] = (unsigned short)(sc - v);
            s.cur2[lane] = sc - v;
        }
        __syncthreads();

        // scatter passes
        for (int p = tid; p < NPG; p += 256) {
            const int c = oi0[(size_t)g * NPG + p] - g * CPG;
            const int slot = atomicAdd(&s.cur[c], 1);
            s.order[slot] = (unsigned short)p;
        }
        if (tid < 128) {
            const int slot = atomicAdd(&s.cur2[s.idx1[tid]], 1);
            s.order2[slot] = (unsigned short)tid;
        }
        __syncthreads();

        // stage 1: gather edge MLP (4 -> 16) + mean
        {
            const int c    = tid >> 1;
            const int half = tid & 1;
            const int beg = (int)s.ofs[c];
            const int n   = s.cur[c] - beg;
            const float cx = s.pos1l[c * 3 + 0];
            const float cy = s.pos1l[c * 3 + 1];
            const float cz = s.pos1l[c * 3 + 2];
            float wb[8], w0r[8], w1r[8], w2r[8], w3r[8];
            #pragma unroll
            for (int j8 = 0; j8 < 8; j8++) {
                const int j = half * 8 + j8;
                wb[j8]  = s.b1l[j];
                w0r[j8] = s.w1l[j];
                w1r[j8] = s.w1l[16 + j];
                w2r[j8] = s.w1l[32 + j];
                w3r[j8] = s.w1l[48 + j];
            }
            float acc[8];
            #pragma unroll
            for (int j8 = 0; j8 < 8; j8++) acc[j8] = 0.0f;
            for (int i = 0; i < n; i++) {
                const float4 pt = s.B.pts[(int)s.order[beg + i]];
                const float rx = pt.y - cx, ry = pt.z - cy, rz = pt.w - cz;
                #pragma unroll
                for (int j8 = 0; j8 < 8; j8++) {
                    float a = wb[j8];
                    a = fmaf(pt.x, w0r[j8], a);
                    a = fmaf(rx,   w1r[j8], a);
                    a = fmaf(ry,   w2r[j8], a);
                    a = fmaf(rz,   w3r[j8], a);
                    acc[j8] += celu1(a);
                }
            }
            const float inv = 1.0f / fmaxf((float)n, 1.0f);
            #pragma unroll
            for (int j8 = 0; j8 < 8; j8++)
                s.agg[c * 16 + half * 8 + j8] = acc[j8] * inv;
        }
        __syncthreads();

        // stage 2: f1 = celu(mean1 @ W1g + b1g)  [128][32] -> fp16
        {
            const int jq = tid & 7;
            const int cg = tid >> 3;
            const float4* Wq = reinterpret_cast<const float4*>(s.w1g); // [16][8]
            float acc[4][4];
            #pragma unroll
            for (int c4 = 0; c4 < 4; c4++)
                #pragma unroll
                for (int u = 0; u < 4; u++) acc[c4][u] = s.b1g[jq * 4 + u];
            #pragma unroll
            for (int k = 0; k < 16; k++) {
                const float4 wv = Wq[k * 8 + jq];
                #pragma unroll
                for (int c4 = 0; c4 < 4; c4++) {
                    const float x = s.agg[(cg * 4 + c4) * 16 + k];
                    FMA4(acc[c4], x, wv);
                }
            }
            #pragma unroll
            for (int c4 = 0; c4 < 4; c4++) {
                const int c = cg * 4 + c4;
                pack2h2(celu1(acc[c4][0]), celu1(acc[c4][1]),
                        celu1(acc[c4][2]), celu1(acc[c4][3]),
                        &s.A.f1h[c * 16 + jq * 2]);
            }
        }
        __syncthreads();

        // stage 3a: edge MLP (35 -> 64) into h2 (fp16), W2l from global
        {
            const int jq = tid & 15;
            const int eg = tid >> 4;
            const float4* Wq = reinterpret_cast<const float4*>(W2l);   // [35][16]
            const float4 bb = reinterpret_cast<const float4*>(s.b2l)[jq];
            float acc[8][4];
            #pragma unroll
            for (int e = 0; e < 8; e++) {
                acc[e][0] = bb.x; acc[e][1] = bb.y; acc[e][2] = bb.z; acc[e][3] = bb.w;
            }
            #pragma unroll
            for (int kq = 0; kq < 8; kq++) {
                const float4 wa = Wq[(kq * 4 + 0) * 16 + jq];
                const float4 wb = Wq[(kq * 4 + 1) * 16 + jq];
                const float4 wc = Wq[(kq * 4 + 2) * 16 + jq];
                const float4 wd = Wq[(kq * 4 + 3) * 16 + jq];
                #pragma unroll
                for (int e = 0; e < 8; e++) {
                    float x0, x1, x2, x3;
                    load4h(&s.A.f1h[(eg * 8 + e) * 16 + kq * 2], x0, x1, x2, x3);
                    FMA4(acc[e], x0, wa);
                    FMA4(acc[e], x1, wb);
                    FMA4(acc[e], x2, wc);
                    FMA4(acc[e], x3, wd);
                }
            }
            #pragma unroll
            for (int k2 = 0; k2 < 3; k2++) {
                const float4 wv = Wq[(32 + k2) * 16 + jq];
                #pragma unroll
                for (int e = 0; e < 8; e++) {
                    const int ee = eg * 8 + e;
                    const float r = s.pos1l[ee * 3 + k2]
                                  - s.pos2l2[gi * 96 + s.idx1[ee] * 3 + k2];
                    FMA4(acc[e], r, wv);
                }
            }
            #pragma unroll
            for (int e = 0; e < 8; e++) {
                const int ee = eg * 8 + e;
                pack2h2(celu1(acc[e][0]), celu1(acc[e][1]),
                        celu1(acc[e][2]), celu1(acc[e][3]),
                        &s.B.h2[ee * 32 + jq * 2]);
            }
        }
        __syncthreads();

        // stage 3b: gather-reduce h2 -> mean2h[gi] [32][64] fp16
        {
            const int c2 = tid >> 3;
            const int f8 = tid & 7;
            const int beg = (int)s.ofs2[c2];
            const int n   = s.cur2[c2] - beg;
            float acc[8];
            #pragma unroll
            for (int k = 0; k < 8; k++) acc[k] = 0.0f;
            for (int i = 0; i < n; i++) {
                const int e = (int)s.order2[beg + i];
                float x0, x1, x2, x3, x4, x5, x6, x7;
                load4h(&s.B.h2[e * 32 + f8 * 4],     x0, x1, x2, x3);
                load4h(&s.B.h2[e * 32 + f8 * 4 + 2], x4, x5, x6, x7);
                acc[0] += x0; acc[1] += x1; acc[2] += x2; acc[3] += x3;
                acc[4] += x4; acc[5] += x5; acc[6] += x6; acc[7] += x7;
            }
            const float inv = 1.0f / fmaxf((float)n, 1.0f);
            pack2h2(acc[0] * inv, acc[1] * inv, acc[2] * inv, acc[3] * inv,
                    &s.mean2h[gi * 1024 + c2 * 32 + f8 * 4]);
            pack2h2(acc[4] * inv, acc[5] * inv, acc[6] * inv, acc[7] * inv,
                    &s.mean2h[gi * 1024 + c2 * 32 + f8 * 4 + 2]);
        }
    }
    __syncthreads();

    // ============ joint stages 4-7 (2 glimpses share every weight load) =====

    // stage 4: f2 = celu(mean2 @ W2g + b2g)  [2][32][128] -> fp16
    {
        const int jq = tid & 31;
        const int cg = tid >> 5;
        const float4* Wq = reinterpret_cast<const float4*>(W2g);  // [64][32]
        const float4 bb = reinterpret_cast<const float4*>(b2g)[jq];
        float acc[2][4][4];
        #pragma unroll
        for (int gi = 0; gi < 2; gi++)
            #pragma unroll
            for (int c4 = 0; c4 < 4; c4++) {
                acc[gi][c4][0] = bb.x; acc[gi][c4][1] = bb.y;
                acc[gi][c4][2] = bb.z; acc[gi][c4][3] = bb.w;
            }
        #pragma unroll 2
        for (int kq = 0; kq < 16; kq++) {
            const float4 wa = Wq[(kq * 4 + 0) * 32 + jq];
            const float4 wb = Wq[(kq * 4 + 1) * 32 + jq];
            const float4 wc = Wq[(kq * 4 + 2) * 32 + jq];
            const float4 wd = Wq[(kq * 4 + 3) * 32 + jq];
            #pragma unroll
            for (int gi = 0; gi < 2; gi++)
                #pragma unroll
                for (int c4 = 0; c4 < 4; c4++) {
                    float x0, x1, x2, x3;
                    load4h(&s.mean2h[gi * 1024 + (cg * 4 + c4) * 32 + kq * 2],
                           x0, x1, x2, x3);
                    FMA4(acc[gi][c4], x0, wa);
                    FMA4(acc[gi][c4], x1, wb);
                    FMA4(acc[gi][c4], x2, wc);
                    FMA4(acc[gi][c4], x3, wd);
                }
        }
        #pragma unroll
        for (int gi = 0; gi < 2; gi++)
            #pragma unroll
            for (int c4 = 0; c4 < 4; c4++)
                pack2h2(celu1(acc[gi][c4][0]), celu1(acc[gi][c4][1]),
                        celu1(acc[gi][c4][2]), celu1(acc[gi][c4][3]),
                        &s.B.f2h[(gi * 32 + cg * 4 + c4) * 64 + jq * 2]);
    }
    __syncthreads();

    // stage 5: level-3 edge MLP (131 -> 128) + mean, both glimpses
    {
        const int jq = tid & 31;
        const int eg = tid >> 5;        // 8 groups x 4 edges
        const float4* Wq = reinterpret_cast<const float4*>(W3l);  // [131][32]
        const float4 bb = reinterpret_cast<const float4*>(b3l)[jq];
        float acc[2][4][4];
        #pragma unroll
        for (int gi = 0; gi < 2; gi++)
            #pragma unroll
            for (int e = 0; e < 4; e++) {
                acc[gi][e][0] = bb.x; acc[gi][e][1] = bb.y;
                acc[gi][e][2] = bb.z; acc[gi][e][3] = bb.w;
            }
        #pragma unroll 2
        for (int kq = 0; kq < 32; kq++) {
            const float4 wa = Wq[(kq * 4 + 0) * 32 + jq];
            const float4 wb = Wq[(kq * 4 + 1) * 32 + jq];
            const float4 wc = Wq[(kq * 4 + 2) * 32 + jq];
            const float4 wd = Wq[(kq * 4 + 3) * 32 + jq];
            #pragma unroll
            for (int gi = 0; gi < 2; gi++)
                #pragma unroll
                for (int e = 0; e < 4; e++) {
                    const int ee = eg * 4 + e;
                    float x0, x1, x2, x3;
                    load4h(&s.B.f2h[(gi * 32 + ee) * 64 + kq * 2], x0, x1, x2, x3);
                    FMA4(acc[gi][e], x0, wa);
                    FMA4(acc[gi][e], x1, wb);
                    FMA4(acc[gi][e], x2, wc);
                    FMA4(acc[gi][e], x3, wd);
                }
        }
        #pragma unroll
        for (int k2 = 0; k2 < 3; k2++) {
            const float4 wv = Wq[(128 + k2) * 32 + jq];
            #pragma unroll
            for (int gi = 0; gi < 2; gi++)
                #pragma unroll
                for (int e = 0; e < 4; e++) {
                    const float r = s.pos2l2[gi * 96 + (eg * 4 + e) * 3 + k2];
                    FMA4(acc[gi][e], r, wv);
                }
        }
        #pragma unroll
        for (int gi = 0; gi < 2; gi++) {
            float4 pv;
            pv.x = celu1(acc[gi][0][0]) + celu1(acc[gi][1][0]) + celu1(acc[gi][2][0]) + celu1(acc[gi][3][0]);
            pv.y = celu1(acc[gi][0][1]) + celu1(acc[gi][1][1]) + celu1(acc[gi][2][1]) + celu1(acc[gi][3][1]);
            pv.z = celu1(acc[gi][0][2]) + celu1(acc[gi][1][2]) + celu1(acc[gi][2][2]) + celu1(acc[gi][3][2]);
            pv.w = celu1(acc[gi][0][3]) + celu1(acc[gi][1][3]) + celu1(acc[gi][2][3]) + celu1(acc[gi][3][3]);
            reinterpret_cast<float4*>(&s.A.psum[gi * 1024 + eg * 128 + jq * 4])[0] = pv;
        }
    }
    __syncthreads();
    {
        const int gi = tid >> 7;
        const int j  = tid & 127;
        float sum = 0.0f;
        #pragma unroll
        for (int e = 0; e < 8; e++) sum += s.A.psum[gi * 1024 + e * 128 + j];
        s.gsum[gi * 128 + j] = sum;
    }
    __syncthreads();

    // stage 6: f = celu((gsum/32) @ W3g + b3g), both glimpses
    {
        const int j = tid;
        float s0 = 0.0f, s1 = 0.0f;
        #pragma unroll 8
        for (int k = 0; k < 128; k++) {
            const float w = W3g[k * 256 + j];
            s0 = fmaf(s.gsum[k],       w, s0);
            s1 = fmaf(s.gsum[128 + k], w, s1);
        }
        const float bj = b3g[j];
        const float f0 = celu1(fmaf(s0, 0.03125f, bj));
        const float f1 = celu1(fmaf(s1, 0.03125f, bj));
        s.fvec[j] = f0;
        s.fvec[256 + j] = f1;
        out[OFF_F + (size_t)g0 * 256 + j] = f0;
        out[OFF_F + (size_t)(g0 + 1) * 256 + j] = f1;
    }
    __syncthreads();

    // stage 7: out = f @ Wlin + blin, both glimpses
    {
        const int j = tid;
        const float bj = blin[j];
        float a0 = bj, a1 = bj;
        #pragma unroll 8
        for (int k = 0; k < 256; k++) {
            const float w = Wlin[k * 256 + j];
            a0 = fmaf(s.fvec[k],       w, a0);
            a1 = fmaf(s.fvec[256 + k], w, a1);
        }
        s.outv[j] = a0;
        s.outv[256 + j] = a1;
    }
    __syncthreads();

    if (tid < 128) {
        #pragma unroll
        for (int gi = 0; gi < 2; gi++) {
            const size_t g = g0 + gi;
            const float mu = s.outv[gi * 256 + tid];
            const float sg = s.outv[gi * 256 + 128 + tid];
            const float sigma = fmaxf(sg, 0.0f) + log1pf(__expf(-fabsf(sg)));
            const float z = fmaf(sigma, eps[g * 128 + tid], mu);
            out[OFF_MU    + g * 128 + tid] = mu;
            out[OFF_SIGMA + g * 128 + tid] = sigma;
            if (tid < 64) out[OFF_ZWHAT + g * 64 + tid] = z;
            else          out[OFF_ZMASK + g * 64 + (tid - 64)] = z;
        }
    }
}

extern "C" void kernel_launch(void* const* d_in, const int* in_sizes, int n_in,
                              void* d_out, int out_size)
{
    const float* rgb  = (const float*)d_in[0];
    const float* pos  = (const float*)d_in[1];
    const float* pos1 = (const float*)d_in[2];
    const float* pos2 = (const float*)d_in[3];
    const int*   oi0  = (const int*)  d_in[4];
    const int*   oi1  = (const int*)  d_in[5];
    const float* eps  = (const float*)d_in[7];
    const float* W1l  = (const float*)d_in[8];
    const float* b1l  = (const float*)d_in[9];
    const float* W1g  = (const float*)d_in[10];
    const float* b1g  = (const float*)d_in[11];
    const float* W2l  = (const float*)d_in[12];
    const float* b2l  = (const float*)d_in[13];
    const float* W2g  = (const float*)d_in[14];
    const float* b2g  = (const float*)d_in[15];
    const float* W3l  = (const float*)d_in[16];
    const float* b3l  = (const float*)d_in[17];
    const float* W3g  = (const float*)d_in[18];
    const float* b3g  = (const float*)d_in[19];
    const float* Wlin = (const float*)d_in[20];
    const float* blin = (const float*)d_in[21];
    float* out = (float*)d_out;

    cudaFuncSetAttribute(vae_fused_kernel,
                         cudaFuncAttributeMaxDynamicSharedMemorySize,
                         (int)sizeof(Smem));
    vae_fused_kernel<<<NG / 2, 256, sizeof(Smem)>>>(
        rgb, pos, pos1, pos2, oi0, oi1, eps,
        W1l, b1l, W1g, b1g, W2l, b2l, W2g, b2g,
        W3l, b3l, W3g, b3g, Wlin, blin, out);
}

// round 10
// speedup vs baseline: 2.3194x; 1.0247x over previous
#include <cuda_runtime.h>
#include <cuda_fp16.h>
#include <math.h>

// Problem constants
#define NG    2048
#define NPG   512
#define CPG   128
#define CPG2  32

// Output layout (float32)
#define OFF_ZWHAT 0
#define OFF_ZMASK 131072
#define OFF_MU    262144
#define OFF_SIGMA 524288
#define OFF_F     786432

struct __align__(16) Smem {
    float w1l[64];      // [4][16]
    float b1l[16];
    float b1g[32];
    float b2l[64];
    float w1g[512];     // [16][32]
    float pos1l[384];   // [128][3]      (per-glimpse, reloaded)
    float pos2l2[192];  // [2][32][3]    (both glimpses)
    int   idx1[128];
    int   cur[128];
    int   cur2[32];
    unsigned short ofs[128];
    unsigned short ofs2[32];
    unsigned short order[512];
    unsigned short order2[128];
    float agg[2048];        // stage1 mean [128][16] (per-glimpse)
    __half2 mean2h[2048];   // [2][32][32h2] = [2][32][64] fp16
    float gsum[256];        // [2][128]
    float fvec[512];        // [2][256]
    float outv[512];        // [2][256]
    union {                 // 8 KB
        __half2 f1h[2048];  // [128][16h2] per-glimpse stage2->3a
        float   psum[2048]; // [2][8][128] joint stage5
    } A;
    union {                 // 16 KB
        float4  pts[512];   // per-glimpse load->stage1 (8 KB)
        __half2 h2[4096];   // [128][32h2] per-glimpse stage3a->3b
        __half2 f2h[4096];  // [2][32][64h2] joint stage4->5
    } B;
};

typedef unsigned long long u64t;

__device__ __forceinline__ float celu1(float x) {
    return fmaxf(x, 0.0f) + (__expf(fminf(x, 0.0f)) - 1.0f);
}

// ---- packed fp32x2 helpers (Blackwell FFMA2) ----
__device__ __forceinline__ u64t splat2(float x) {
    u64t r; asm("mov.b64 %0, {%1, %1};" : "=l"(r) : "f"(x)); return r;
}
__device__ __forceinline__ u64t pack2(float lo, float hi) {
    u64t r; asm("mov.b64 %0, {%1, %2};" : "=l"(r) : "f"(lo), "f"(hi)); return r;
}
__device__ __forceinline__ void unpack2(u64t v, float& lo, float& hi) {
    asm("mov.b64 {%0, %1}, %2;" : "=f"(lo), "=f"(hi) : "l"(v));
}
__device__ __forceinline__ void ffma2(u64t& acc, u64t a, u64t b) {
    asm("fma.rn.f32x2 %0, %1, %2, %0;" : "+l"(acc) : "l"(a), "l"(b));
}
// acc pair (2 x u64 = 4 fp32 outputs) += splat * packed-weight-quad
#define FMA2P(accp, xs2, wv2) \
    { ffma2((accp)[0], (xs2), (wv2).x); ffma2((accp)[1], (xs2), (wv2).y); }

#define FMA4(Aacc, xs, wv) \
    { Aacc[0] = fmaf((xs), (wv).x, Aacc[0]); Aacc[1] = fmaf((xs), (wv).y, Aacc[1]); \
      Aacc[2] = fmaf((xs), (wv).z, Aacc[2]); Aacc[3] = fmaf((xs), (wv).w, Aacc[3]); }

__device__ __forceinline__ void pack2h2(float a0, float a1, float a2, float a3,
                                        __half2* dst) {
    const __half2 h0 = __floats2half2_rn(a0, a1);
    const __half2 h1 = __floats2half2_rn(a2, a3);
    float2 pk;
    pk.x = __uint_as_float(*reinterpret_cast<const unsigned int*>(&h0));
    pk.y = __uint_as_float(*reinterpret_cast<const unsigned int*>(&h1));
    *reinterpret_cast<float2*>(dst) = pk;
}

__device__ __forceinline__ void load4h(const __half2* src, float& x0, float& x1,
                                       float& x2, float& x3) {
    const float2 raw = *reinterpret_cast<const float2*>(src);
    const __half2 ha = *reinterpret_cast<const __half2*>(&raw.x);
    const __half2 hb = *reinterpret_cast<const __half2*>(&raw.y);
    const float2 fa = __half22float2(ha);
    const float2 fb = __half22float2(hb);
    x0 = fa.x; x1 = fa.y; x2 = fb.x; x3 = fb.y;
}

__global__ void __launch_bounds__(256, 3)
vae_fused_kernel(const float* __restrict__ rgb,  const float* __restrict__ pos,
                 const float* __restrict__ pos1, const float* __restrict__ pos2,
                 const int*   __restrict__ oi0,  const int* __restrict__ oi1,
                 const float* __restrict__ eps,
                 const float* __restrict__ W1l, const float* __restrict__ b1l,
                 const float* __restrict__ W1g, const float* __restrict__ b1g,
                 const float* __restrict__ W2l, const float* __restrict__ b2l,
                 const float* __restrict__ W2g, const float* __restrict__ b2g,
                 const float* __restrict__ W3l, const float* __restrict__ b3l,
                 const float* __restrict__ W3g, const float* __restrict__ b3g,
                 const float* __restrict__ Wlin, const float* __restrict__ blin,
                 float* __restrict__ out)
{
    extern __shared__ unsigned char smem_raw[];
    Smem& s = *reinterpret_cast<Smem*>(smem_raw);
    const int tid  = threadIdx.x;
    const int lane = tid & 31;
    const int g0   = blockIdx.x * 2;

    // ---------------- preamble ----------------------------------------------
    for (int i = tid; i < 64;  i += 256) s.w1l[i] = W1l[i];
    if (tid < 16) s.b1l[tid] = b1l[tid];
    if (tid < 32) s.b1g[tid] = b1g[tid];
    if (tid < 64) s.b2l[tid] = b2l[tid];
    for (int i = tid; i < 512; i += 256) s.w1g[i] = W1g[i];
    if (tid < 192) s.pos2l2[tid] = pos2[(size_t)g0 * 96 + tid];

    // ============ per-glimpse stages 1-3 ====================================
    for (int gi = 0; gi < 2; gi++) {
        const int g = g0 + gi;
        __syncthreads();
        if (tid < 128) s.cur[tid] = 0;
        if (tid < 32)  s.cur2[tid] = 0;
        for (int i = tid; i < 384; i += 256) s.pos1l[i] = pos1[(size_t)g * 384 + i];
        __syncthreads();

        // count phase
        if (tid < 128) {
            const int c2 = (int)(oi1[(size_t)g * 128 + tid] - g * CPG2);
            s.idx1[tid] = c2;
            atomicAdd(&s.cur2[c2], 1);
        }
        for (int p = tid; p < NPG; p += 256) {
            const size_t e = (size_t)g * NPG + p;
            float4 pt;
            pt.x = rgb[e];
            pt.y = pos[e * 3 + 0];
            pt.z = pos[e * 3 + 1];
            pt.w = pos[e * 3 + 2];
            s.B.pts[p] = pt;
            atomicAdd(&s.cur[oi0[e] - g * CPG], 1);
        }
        __syncthreads();

        // prefix sums; cur becomes alloc cursor
        if (tid < 32) {
            int v0 = s.cur[lane * 4 + 0], v1 = s.cur[lane * 4 + 1];
            int v2 = s.cur[lane * 4 + 2], v3 = s.cur[lane * 4 + 3];
            int lsum = v0 + v1 + v2 + v3;
            int sc = lsum;
            #pragma unroll
            for (int off = 1; off < 32; off <<= 1) {
                int n = __shfl_up_sync(0xffffffffu, sc, off);
                if (lane >= off) sc += n;
            }
            int e0 = sc - lsum;
            int e1 = e0 + v0, e2 = e1 + v1, e3 = e2 + v2;
            s.ofs[lane * 4 + 0] = (unsigned short)e0; s.cur[lane * 4 + 0] = e0;
            s.ofs[lane * 4 + 1] = (unsigned short)e1; s.cur[lane * 4 + 1] = e1;
            s.ofs[lane * 4 + 2] = (unsigned short)e2; s.cur[lane * 4 + 2] = e2;
            s.ofs[lane * 4 + 3] = (unsigned short)e3; s.cur[lane * 4 + 3] = e3;
        } else if (tid < 64) {
            int v = s.cur2[lane];
            int sc = v;
            #pragma unroll
            for (int off = 1; off < 32; off <<= 1) {
                int n = __shfl_up_sync(0xffffffffu, sc, off);
                if (lane >= off) sc += n;
            }
            s.ofs2[lane] = (unsigned short)(sc - v);
            s.cur2[lane] = sc - v;
        }
        __syncthreads();

        // scatter passes
        for (int p = tid; p < NPG; p += 256) {
            const int c = oi0[(size_t)g * NPG + p] - g * CPG;
            const int slot = atomicAdd(&s.cur[c], 1);
            s.order[slot] = (unsigned short)p;
        }
        if (tid < 128) {
            const int slot = atomicAdd(&s.cur2[s.idx1[tid]], 1);
            s.order2[slot] = (unsigned short)tid;
        }
        __syncthreads();

        // stage 1: gather edge MLP (4 -> 16) + mean
        {
            const int c    = tid >> 1;
            const int half = tid & 1;
            const int beg = (int)s.ofs[c];
            const int n   = s.cur[c] - beg;
            const float cx = s.pos1l[c * 3 + 0];
            const float cy = s.pos1l[c * 3 + 1];
            const float cz = s.pos1l[c * 3 + 2];
            float wb[8], w0r[8], w1r[8], w2r[8], w3r[8];
            #pragma unroll
            for (int j8 = 0; j8 < 8; j8++) {
                const int j = half * 8 + j8;
                wb[j8]  = s.b1l[j];
                w0r[j8] = s.w1l[j];
                w1r[j8] = s.w1l[16 + j];
                w2r[j8] = s.w1l[32 + j];
                w3r[j8] = s.w1l[48 + j];
            }
            float acc[8];
            #pragma unroll
            for (int j8 = 0; j8 < 8; j8++) acc[j8] = 0.0f;
            for (int i = 0; i < n; i++) {
                const float4 pt = s.B.pts[(int)s.order[beg + i]];
                const float rx = pt.y - cx, ry = pt.z - cy, rz = pt.w - cz;
                #pragma unroll
                for (int j8 = 0; j8 < 8; j8++) {
                    float a = wb[j8];
                    a = fmaf(pt.x, w0r[j8], a);
                    a = fmaf(rx,   w1r[j8], a);
                    a = fmaf(ry,   w2r[j8], a);
                    a = fmaf(rz,   w3r[j8], a);
                    acc[j8] += celu1(a);
                }
            }
            const float inv = 1.0f / fmaxf((float)n, 1.0f);
            #pragma unroll
            for (int j8 = 0; j8 < 8; j8++)
                s.agg[c * 16 + half * 8 + j8] = acc[j8] * inv;
        }
        __syncthreads();

        // stage 2: f1 = celu(mean1 @ W1g + b1g)  [128][32] -> fp16
        {
            const int jq = tid & 7;
            const int cg = tid >> 3;
            const float4* Wq = reinterpret_cast<const float4*>(s.w1g); // [16][8]
            float acc[4][4];
            #pragma unroll
            for (int c4 = 0; c4 < 4; c4++)
                #pragma unroll
                for (int u = 0; u < 4; u++) acc[c4][u] = s.b1g[jq * 4 + u];
            #pragma unroll
            for (int k = 0; k < 16; k++) {
                const float4 wv = Wq[k * 8 + jq];
                #pragma unroll
                for (int c4 = 0; c4 < 4; c4++) {
                    const float x = s.agg[(cg * 4 + c4) * 16 + k];
                    FMA4(acc[c4], x, wv);
                }
            }
            #pragma unroll
            for (int c4 = 0; c4 < 4; c4++) {
                const int c = cg * 4 + c4;
                pack2h2(celu1(acc[c4][0]), celu1(acc[c4][1]),
                        celu1(acc[c4][2]), celu1(acc[c4][3]),
                        &s.A.f1h[c * 16 + jq * 2]);
            }
        }
        __syncthreads();

        // stage 3a: edge MLP (35 -> 64) into h2 (fp16) — packed FFMA2
        {
            const int jq = tid & 15;
            const int eg = tid >> 4;
            const ulonglong2* Wq = reinterpret_cast<const ulonglong2*>(W2l); // [35][16]q
            const float4 bb = reinterpret_cast<const float4*>(s.b2l)[jq];
            const u64t b01 = pack2(bb.x, bb.y), b23 = pack2(bb.z, bb.w);
            u64t acc[8][2];
            #pragma unroll
            for (int e = 0; e < 8; e++) { acc[e][0] = b01; acc[e][1] = b23; }
            #pragma unroll
            for (int kq = 0; kq < 8; kq++) {
                const ulonglong2 wa = Wq[(kq * 4 + 0) * 16 + jq];
                const ulonglong2 wb = Wq[(kq * 4 + 1) * 16 + jq];
                const ulonglong2 wc = Wq[(kq * 4 + 2) * 16 + jq];
                const ulonglong2 wd = Wq[(kq * 4 + 3) * 16 + jq];
                #pragma unroll
                for (int e = 0; e < 8; e++) {
                    float x0, x1, x2, x3;
                    load4h(&s.A.f1h[(eg * 8 + e) * 16 + kq * 2], x0, x1, x2, x3);
                    const u64t s0 = splat2(x0), s1 = splat2(x1);
                    const u64t s2 = splat2(x2), s3 = splat2(x3);
                    FMA2P(acc[e], s0, wa);
                    FMA2P(acc[e], s1, wb);
                    FMA2P(acc[e], s2, wc);
                    FMA2P(acc[e], s3, wd);
                }
            }
            #pragma unroll
            for (int k2 = 0; k2 < 3; k2++) {
                const ulonglong2 wv = Wq[(32 + k2) * 16 + jq];
                #pragma unroll
                for (int e = 0; e < 8; e++) {
                    const int ee = eg * 8 + e;
                    const float r = s.pos1l[ee * 3 + k2]
                                  - s.pos2l2[gi * 96 + s.idx1[ee] * 3 + k2];
                    const u64t r2 = splat2(r);
                    FMA2P(acc[e], r2, wv);
                }
            }
            #pragma unroll
            for (int e = 0; e < 8; e++) {
                const int ee = eg * 8 + e;
                float a0, a1, a2, a3;
                unpack2(acc[e][0], a0, a1);
                unpack2(acc[e][1], a2, a3);
                pack2h2(celu1(a0), celu1(a1), celu1(a2), celu1(a3),
                        &s.B.h2[ee * 32 + jq * 2]);
            }
        }
        __syncthreads();

        // stage 3b: gather-reduce h2 -> mean2h[gi] [32][64] fp16
        {
            const int c2 = tid >> 3;
            const int f8 = tid & 7;
            const int beg = (int)s.ofs2[c2];
            const int n   = s.cur2[c2] - beg;
            float acc[8];
            #pragma unroll
            for (int k = 0; k < 8; k++) acc[k] = 0.0f;
            for (int i = 0; i < n; i++) {
                const int e = (int)s.order2[beg + i];
                float x0, x1, x2, x3, x4, x5, x6, x7;
                load4h(&s.B.h2[e * 32 + f8 * 4],     x0, x1, x2, x3);
                load4h(&s.B.h2[e * 32 + f8 * 4 + 2], x4, x5, x6, x7);
                acc[0] += x0; acc[1] += x1; acc[2] += x2; acc[3] += x3;
                acc[4] += x4; acc[5] += x5; acc[6] += x6; acc[7] += x7;
            }
            const float inv = 1.0f / fmaxf((float)n, 1.0f);
            pack2h2(acc[0] * inv, acc[1] * inv, acc[2] * inv, acc[3] * inv,
                    &s.mean2h[gi * 1024 + c2 * 32 + f8 * 4]);
            pack2h2(acc[4] * inv, acc[5] * inv, acc[6] * inv, acc[7] * inv,
                    &s.mean2h[gi * 1024 + c2 * 32 + f8 * 4 + 2]);
        }
    }
    __syncthreads();

    // ============ joint stages 4-7 ==========================================

    // stage 4: f2 = celu(mean2 @ W2g + b2g)  [2][32][128] -> fp16 — FFMA2
    {
        const int jq = tid & 31;
        const int cg = tid >> 5;
        const ulonglong2* Wq = reinterpret_cast<const ulonglong2*>(W2g); // [64][32]q
        const float4 bb = reinterpret_cast<const float4*>(b2g)[jq];
        const u64t b01 = pack2(bb.x, bb.y), b23 = pack2(bb.z, bb.w);
        u64t acc[2][4][2];
        #pragma unroll
        for (int gi = 0; gi < 2; gi++)
            #pragma unroll
            for (int c4 = 0; c4 < 4; c4++) { acc[gi][c4][0] = b01; acc[gi][c4][1] = b23; }
        #pragma unroll 2
        for (int kq = 0; kq < 16; kq++) {
            const ulonglong2 wa = Wq[(kq * 4 + 0) * 32 + jq];
            const ulonglong2 wb = Wq[(kq * 4 + 1) * 32 + jq];
            const ulonglong2 wc = Wq[(kq * 4 + 2) * 32 + jq];
            const ulonglong2 wd = Wq[(kq * 4 + 3) * 32 + jq];
            #pragma unroll
            for (int gi = 0; gi < 2; gi++)
                #pragma unroll
                for (int c4 = 0; c4 < 4; c4++) {
                    float x0, x1, x2, x3;
                    load4h(&s.mean2h[gi * 1024 + (cg * 4 + c4) * 32 + kq * 2],
                           x0, x1, x2, x3);
                    const u64t s0 = splat2(x0), s1 = splat2(x1);
                    const u64t s2 = splat2(x2), s3 = splat2(x3);
                    FMA2P(acc[gi][c4], s0, wa);
                    FMA2P(acc[gi][c4], s1, wb);
                    FMA2P(acc[gi][c4], s2, wc);
                    FMA2P(acc[gi][c4], s3, wd);
                }
        }
        #pragma unroll
        for (int gi = 0; gi < 2; gi++)
            #pragma unroll
            for (int c4 = 0; c4 < 4; c4++) {
                float a0, a1, a2, a3;
                unpack2(acc[gi][c4][0], a0, a1);
                unpack2(acc[gi][c4][1], a2, a3);
                pack2h2(celu1(a0), celu1(a1), celu1(a2), celu1(a3),
                        &s.B.f2h[(gi * 32 + cg * 4 + c4) * 64 + jq * 2]);
            }
    }
    __syncthreads();

    // stage 5: level-3 edge MLP (131 -> 128) + mean — FFMA2
    {
        const int jq = tid & 31;
        const int eg = tid >> 5;        // 8 groups x 4 edges
        const ulonglong2* Wq = reinterpret_cast<const ulonglong2*>(W3l); // [131][32]q
        const float4 bb = reinterpret_cast<const float4*>(b3l)[jq];
        const u64t b01 = pack2(bb.x, bb.y), b23 = pack2(bb.z, bb.w);
        u64t acc[2][4][2];
        #pragma unroll
        for (int gi = 0; gi < 2; gi++)
            #pragma unroll
            for (int e = 0; e < 4; e++) { acc[gi][e][0] = b01; acc[gi][e][1] = b23; }
        #pragma unroll 2
        for (int kq = 0; kq < 32; kq++) {
            const ulonglong2 wa = Wq[(kq * 4 + 0) * 32 + jq];
            const ulonglong2 wb = Wq[(kq * 4 + 1) * 32 + jq];
            const ulonglong2 wc = Wq[(kq * 4 + 2) * 32 + jq];
            const ulonglong2 wd = Wq[(kq * 4 + 3) * 32 + jq];
            #pragma unroll
            for (int gi = 0; gi < 2; gi++)
                #pragma unroll
                for (int e = 0; e < 4; e++) {
                    const int ee = eg * 4 + e;
                    float x0, x1, x2, x3;
                    load4h(&s.B.f2h[(gi * 32 + ee) * 64 + kq * 2], x0, x1, x2, x3);
                    const u64t s0 = splat2(x0), s1 = splat2(x1);
                    const u64t s2 = splat2(x2), s3 = splat2(x3);
                    FMA2P(acc[gi][e], s0, wa);
                    FMA2P(acc[gi][e], s1, wb);
                    FMA2P(acc[gi][e], s2, wc);
                    FMA2P(acc[gi][e], s3, wd);
                }
        }
        #pragma unroll
        for (int k2 = 0; k2 < 3; k2++) {
            const ulonglong2 wv = Wq[(128 + k2) * 32 + jq];
            #pragma unroll
            for (int gi = 0; gi < 2; gi++)
                #pragma unroll
                for (int e = 0; e < 4; e++) {
                    const float r = s.pos2l2[gi * 96 + (eg * 4 + e) * 3 + k2];
                    const u64t r2 = splat2(r);
                    FMA2P(acc[gi][e], r2, wv);
                }
        }
        #pragma unroll
        for (int gi = 0; gi < 2; gi++) {
            float a[4][4];
            #pragma unroll
            for (int e = 0; e < 4; e++) {
                unpack2(acc[gi][e][0], a[e][0], a[e][1]);
                unpack2(acc[gi][e][1], a[e][2], a[e][3]);
            }
            float4 pv;
            pv.x = celu1(a[0][0]) + celu1(a[1][0]) + celu1(a[2][0]) + celu1(a[3][0]);
            pv.y = celu1(a[0][1]) + celu1(a[1][1]) + celu1(a[2][1]) + celu1(a[3][1]);
            pv.z = celu1(a[0][2]) + celu1(a[1][2]) + celu1(a[2][2]) + celu1(a[3][2]);
            pv.w = celu1(a[0][3]) + celu1(a[1][3]) + celu1(a[2][3]) + celu1(a[3][3]);
            reinterpret_cast<float4*>(&s.A.psum[gi * 1024 + eg * 128 + jq * 4])[0] = pv;
        }
    }
    __syncthreads();
    {
        const int gi = tid >> 7;
        const int j  = tid & 127;
        float sum = 0.0f;
        #pragma unroll
        for (int e = 0; e < 8; e++) sum += s.A.psum[gi * 1024 + e * 128 + j];
        s.gsum[gi * 128 + j] = sum;
    }
    __syncthreads();

    // stage 6: f = celu((gsum/32) @ W3g + b3g), both glimpses
    {
        const int j = tid;
        float s0 = 0.0f, s1 = 0.0f;
        #pragma unroll 8
        for (int k = 0; k < 128; k++) {
            const float w = W3g[k * 256 + j];
            s0 = fmaf(s.gsum[k],       w, s0);
            s1 = fmaf(s.gsum[128 + k], w, s1);
        }
        const float bj = b3g[j];
        const float f0 = celu1(fmaf(s0, 0.03125f, bj));
        const float f1 = celu1(fmaf(s1, 0.03125f, bj));
        s.fvec[j] = f0;
        s.fvec[256 + j] = f1;
        out[OFF_F + (size_t)g0 * 256 + j] = f0;
        out[OFF_F + (size_t)(g0 + 1) * 256 + j] = f1;
    }
    __syncthreads();

    // stage 7: out = f @ Wlin + blin, both glimpses
    {
        const int j = tid;
        const float bj = blin[j];
        float a0 = bj, a1 = bj;
        #pragma unroll 8
        for (int k = 0; k < 256; k++) {
            const float w = Wlin[k * 256 + j];
            a0 = fmaf(s.fvec[k],       w, a0);
            a1 = fmaf(s.fvec[256 + k], w, a1);
        }
        s.outv[j] = a0;
        s.outv[256 + j] = a1;
    }
    __syncthreads();

    if (tid < 128) {
        #pragma unroll
        for (int gi = 0; gi < 2; gi++) {
            const size_t g = g0 + gi;
            const float mu = s.outv[gi * 256 + tid];
            const float sg = s.outv[gi * 256 + 128 + tid];
            const float sigma = fmaxf(sg, 0.0f) + log1pf(__expf(-fabsf(sg)));
            const float z = fmaf(sigma, eps[g * 128 + tid], mu);
            out[OFF_MU    + g * 128 + tid] = mu;
            out[OFF_SIGMA + g * 128 + tid] = sigma;
            if (tid < 64) out[OFF_ZWHAT + g * 64 + tid] = z;
            else          out[OFF_ZMASK + g * 64 + (tid - 64)] = z;
        }
    }
}

extern "C" void kernel_launch(void* const* d_in, const int* in_sizes, int n_in,
                              void* d_out, int out_size)
{
    const float* rgb  = (const float*)d_in[0];
    const float* pos  = (const float*)d_in[1];
    const float* pos1 = (const float*)d_in[2];
    const float* pos2 = (const float*)d_in[3];
    const int*   oi0  = (const int*)  d_in[4];
    const int*   oi1  = (const int*)  d_in[5];
    const float* eps  = (const float*)d_in[7];
    const float* W1l  = (const float*)d_in[8];
    const float* b1l  = (const float*)d_in[9];
    const float* W1g  = (const float*)d_in[10];
    const float* b1g  = (const float*)d_in[11];
    const float* W2l  = (const float*)d_in[12];
    const float* b2l  = (const float*)d_in[13];
    const float* W2g  = (const float*)d_in[14];
    const float* b2g  = (const float*)d_in[15];
    const float* W3l  = (const float*)d_in[16];
    const float* b3l  = (const float*)d_in[17];
    const float* W3g  = (const float*)d_in[18];
    const float* b3g  = (const float*)d_in[19];
    const float* Wlin = (const float*)d_in[20];
    const float* blin = (const float*)d_in[21];
    float* out = (float*)d_out;

    cudaFuncSetAttribute(vae_fused_kernel,
                         cudaFuncAttributeMaxDynamicSharedMemorySize,
                         (int)sizeof(Smem));
    vae_fused_kernel<<<NG / 2, 256, sizeof(Smem)>>>(
        rgb, pos, pos1, pos2, oi0, oi1, eps,
        W1l, b1l, W1g, b1g, W2l, b2l, W2g, b2g,
        W3l, b3l, W3g, b3g, Wlin, blin, out);
}